// round 14
// baseline (speedup 1.0000x reference)
#include <cuda_runtime.h>
#include <cuda_bf16.h>
#include <cstdint>
#include <math.h>

// ---- problem constants ----
#define BB    16
#define HH    128
#define WWID  128
#define CC    192
#define WS    8
#define SHIFTV 4
#define HEADS 6
#define NN    64
#define HD    32
#define TT    (BB*HH*WWID)   // 262144
#define NWIN  256
#define BWIN  (BB*NWIN)      // 4096
#define C3    (3*CC)         // 576
#define C4    (4*CC)         // 768
#define SCALE 0.17677669529663687f

// ---- scratch ----
__device__ __align__(16) __nv_bfloat16 g_xw  [(size_t)TT*CC];
__device__ __align__(16) __nv_bfloat16 g_qkv [(size_t)TT*C3];
__device__ __align__(16) __nv_bfloat16 g_attn[(size_t)TT*CC];
__device__ __align__(16) float         g_h   [(size_t)TT*CC];
__device__ __align__(16) __nv_bfloat16 g_m1  [(size_t)TT*C4];
__device__ __align__(16) __nv_bfloat16 g_wb  [C3*CC + CC*CC + C4*CC + CC*C4];

#define WB_QKV  0
#define WB_PROJ (C3*CC)
#define WB_FC1  (WB_PROJ + CC*CC)
#define WB_FC2  (WB_FC1 + C4*CC)

// ---- helpers ----
__device__ __forceinline__ uint32_t smem_u32(const void* p) {
    uint32_t a;
    asm("{ .reg .u64 t; cvta.to.shared.u64 t, %1; cvt.u32.u64 %0, t; }" : "=r"(a) : "l"(p));
    return a;
}
__device__ __forceinline__ uint32_t packbf2(float lo, float hi) {
    uint32_t r;
    asm("cvt.rn.bf16x2.f32 %0, %1, %2;" : "=r"(r) : "f"(hi), "f"(lo));
    return r;
}
__device__ __forceinline__ void ldm4(uint32_t r[4], uint32_t addr) {
    asm volatile("ldmatrix.sync.aligned.m8n8.x4.shared.b16 {%0,%1,%2,%3}, [%4];"
        : "=r"(r[0]), "=r"(r[1]), "=r"(r[2]), "=r"(r[3]) : "r"(addr));
}
__device__ __forceinline__ void ldm4t(uint32_t r[4], uint32_t addr) {
    asm volatile("ldmatrix.sync.aligned.m8n8.x4.trans.shared.b16 {%0,%1,%2,%3}, [%4];"
        : "=r"(r[0]), "=r"(r[1]), "=r"(r[2]), "=r"(r[3]) : "r"(addr));
}
__device__ __forceinline__ void mma_bf16(float c[4], const uint32_t a[4], uint32_t b0, uint32_t b1) {
    asm volatile("mma.sync.aligned.m16n8k16.row.col.f32.bf16.bf16.f32 "
        "{%0,%1,%2,%3},{%4,%5,%6,%7},{%8,%9},{%0,%1,%2,%3};"
        : "+f"(c[0]), "+f"(c[1]), "+f"(c[2]), "+f"(c[3])
        : "r"(a[0]), "r"(a[1]), "r"(a[2]), "r"(a[3]), "r"(b0), "r"(b1));
}
#define CP16(dst, src) asm volatile("cp.async.cg.shared.global [%0], [%1], 16;" :: "r"(dst), "l"(src))
#define CPCA16(dst, src) asm volatile("cp.async.ca.shared.global [%0], [%1], 16;" :: "r"(dst), "l"(src))
#define CP4(dst, src)  asm volatile("cp.async.ca.shared.global [%0], [%1], 4;"  :: "r"(dst), "l"(src))
#define CPCOMMIT() asm volatile("cp.async.commit_group;" ::: "memory")
#define CPWAIT(n)  asm volatile("cp.async.wait_group %0;" :: "n"(n) : "memory")

__device__ __forceinline__ int win_to_orig(int tw) {
    int n  = tw & 63;
    int bw = tw >> 6;
    int ww = bw & 15;
    int wh = (bw >> 4) & 15;
    int b  = bw >> 8;
    int ri = n >> 3, ci = n & 7;
    int r = (wh * 8 + ri + SHIFTV) & 127;
    int c = (ww * 8 + ci + SHIFTV) & 127;
    return (b << 14) + (r << 7) + c;
}

// ================= fused weight convert (all 4 weights, 1 launch) =================
#define WTOT (C3*CC + CC*CC + C4*CC + CC*C4)
__global__ void wconv4(const float* __restrict__ s0, const float* __restrict__ s1,
                       const float* __restrict__ s2, const float* __restrict__ s3,
                       __nv_bfloat16* __restrict__ dst) {
    int i = (blockIdx.x * 256 + threadIdx.x) * 4;
    if (i >= WTOT) return;
    const int n0 = C3 * CC, n1 = n0 + CC * CC, n2 = n1 + C4 * CC;
    const float* src;
    int off;
    if (i < n0)      { src = s0; off = i; }
    else if (i < n1) { src = s1; off = i - n0; }
    else if (i < n2) { src = s2; off = i - n1; }
    else             { src = s3; off = i - n2; }
    float4 f = *(const float4*)(src + off);
    *(uint2*)(dst + i) = make_uint2(packbf2(f.x, f.y), packbf2(f.z, f.w));
}

// ================= LN1 (gather + fp32 -> bf16) =================
__global__ void ln_kernel(const float* __restrict__ in, const float* __restrict__ gg,
                          const float* __restrict__ bb, __nv_bfloat16* __restrict__ out) {
    int warp = blockIdx.x * (blockDim.x >> 5) + (threadIdx.x >> 5);
    int lane = threadIdx.x & 31;
    int src = win_to_orig(warp);
    const float* ip = in + (size_t)src * CC;
    float v[6];
    float s = 0.f, s2 = 0.f;
#pragma unroll
    for (int k = 0; k < 6; k++) {
        v[k] = ip[lane + 32 * k];
        s += v[k]; s2 += v[k] * v[k];
    }
#pragma unroll
    for (int o = 16; o; o >>= 1) {
        s  += __shfl_xor_sync(0xffffffffu, s,  o);
        s2 += __shfl_xor_sync(0xffffffffu, s2, o);
    }
    float mean = s * (1.f / CC);
    float var  = s2 * (1.f / CC) - mean * mean;
    float rstd = rsqrtf(var + 1e-5f);
    __nv_bfloat16* op = out + (size_t)warp * CC;
#pragma unroll
    for (int k = 0; k < 6; k++) {
        int c = lane + 32 * k;
        op[c] = __float2bfloat16((v[k] - mean) * rstd * gg[c] + bb[c]);
    }
}

// ================= bf16 mma GEMM =================
// BM=128, BN=192, BK=64h; 256 threads; warp grid 2x4; warp tile 64x48.
#define BM 128
#define BN 192
#define BKH 64
#define AST (BM*128)
#define BST (BN*128)
#define STAGE (AST+BST)
#define GSMEM (2*STAGE)   // 81920

template<int EPI>
__global__ __launch_bounds__(256, 2)
void bgemm(const __nv_bfloat16* __restrict__ A, const __nv_bfloat16* __restrict__ W,
           const float* __restrict__ bias, void* __restrict__ outv,
           const float* __restrict__ aux, int Ntot, int K,
           const float* __restrict__ g2, const float* __restrict__ b2,
           __nv_bfloat16* __restrict__ xwout) {
    extern __shared__ char smc[];
    uint32_t sbase = smem_u32(smc);
    int tid = threadIdx.x, lane = tid & 31, wid = tid >> 5;
    int m0 = blockIdx.y * BM, n0 = blockIdx.x * BN;
    int wm = (wid & 1) * 64, wn = (wid >> 1) * 48;
    int g = lane >> 2, t = lane & 3;
    int l8 = lane & 7, msel = lane >> 3;

    float acc[4][6][4];
#pragma unroll
    for (int i = 0; i < 4; i++)
#pragma unroll
        for (int j = 0; j < 6; j++)
#pragma unroll
            for (int q = 0; q < 4; q++) acc[i][j][q] = 0.f;

    const __nv_bfloat16* Abp = A + (size_t)m0 * K;
    const __nv_bfloat16* Wbp = W + (size_t)n0 * K;

#define ISSUE(kt, buf) { \
    uint32_t sA_ = sbase + (buf) * STAGE; \
    uint32_t sB_ = sA_ + AST; \
    _Pragma("unroll") for (int i2 = 0; i2 < 4; i2++) { int id = tid + 256 * i2; \
        int row = id >> 3, cc_ = id & 7; \
        CP16(sA_ + (uint32_t)(row * 128 + ((cc_ ^ (row & 7)) * 16)), \
             Abp + (size_t)row * K + (kt) * BKH + cc_ * 8); } \
    _Pragma("unroll") for (int i2 = 0; i2 < 6; i2++) { int id = tid + 256 * i2; \
        int row = id >> 3, cc_ = id & 7; \
        CPCA16(sB_ + (uint32_t)(row * 128 + ((cc_ ^ (row & 7)) * 16)), \
             Wbp + (size_t)row * K + (kt) * BKH + cc_ * 8); } \
    CPCOMMIT(); }

#define CMP(buf) { \
    uint32_t sA_ = sbase + (buf) * STAGE; \
    uint32_t sB_ = sA_ + AST; \
    _Pragma("unroll") for (int s = 0; s < 4; s++) { \
        uint32_t af[4][4]; \
        _Pragma("unroll") for (int i2 = 0; i2 < 4; i2++) \
            ldm4(af[i2], sA_ + (uint32_t)(wm + 16 * i2 + l8 + ((msel & 1) << 3)) * 128 \
                             + (uint32_t)(((2 * s + (msel >> 1)) ^ l8) * 16)); \
        _Pragma("unroll") for (int j = 0; j < 3; j++) { \
            uint32_t bq[4]; \
            ldm4(bq, sB_ + (uint32_t)(wn + 16 * j + l8 + ((msel >> 1) << 3)) * 128 \
                         + (uint32_t)(((2 * s + (msel & 1)) ^ l8) * 16)); \
            _Pragma("unroll") for (int i2 = 0; i2 < 4; i2++) { \
                mma_bf16(acc[i2][2 * j + 0], af[i2], bq[0], bq[1]); \
                mma_bf16(acc[i2][2 * j + 1], af[i2], bq[2], bq[3]); } } } }

    const int KT = K / BKH;
    ISSUE(0, 0);
    for (int kt = 0; kt < KT; kt++) {
        if (kt + 1 < KT) { ISSUE(kt + 1, (kt + 1) & 1); CPWAIT(1); }
        else             { CPWAIT(0); }
        __syncthreads();
        CMP(kt & 1);
        __syncthreads();
    }
#undef ISSUE
#undef CMP

    if (EPI == 0 || EPI == 2) {
        __nv_bfloat16* outp = (__nv_bfloat16*)outv;
#pragma unroll
        for (int i2 = 0; i2 < 4; i2++)
#pragma unroll
            for (int half = 0; half < 2; half++) {
                int r = m0 + wm + 16 * i2 + g + 8 * half;
                size_t ob = (size_t)r * Ntot;
#pragma unroll
                for (int j2 = 0; j2 < 6; j2++) {
                    int c = n0 + wn + 8 * j2 + 2 * t;
                    float v0 = acc[i2][j2][half * 2 + 0] + bias[c];
                    float v1 = acc[i2][j2][half * 2 + 1] + bias[c + 1];
                    if (EPI == 2) {
                        v0 = 0.5f * v0 * (1.f + erff(v0 * 0.70710678118654752f));
                        v1 = 0.5f * v1 * (1.f + erff(v1 * 0.70710678118654752f));
                    }
                    *(uint32_t*)(outp + ob + c) = packbf2(v0, v1);
                }
            }
    } else if (EPI == 3) {
        float* outp = (float*)outv;
#pragma unroll
        for (int i2 = 0; i2 < 4; i2++)
#pragma unroll
            for (int half = 0; half < 2; half++) {
                int r = m0 + wm + 16 * i2 + g + 8 * half;
                size_t ob = (size_t)r * CC;
#pragma unroll
                for (int j2 = 0; j2 < 6; j2++) {
                    int c = n0 + wn + 8 * j2 + 2 * t;
                    float2 a2 = *(const float2*)(aux + ob + c);
                    float v0 = acc[i2][j2][half * 2 + 0] + bias[c] + a2.x;
                    float v1 = acc[i2][j2][half * 2 + 1] + bias[c + 1] + a2.y;
                    *(float2*)(outp + ob + c) = make_float2(v0, v1);
                }
            }
    } else {
        // EPI 1: proj -> h = acc + bias + x (scatter); fused LN2 -> xw bf16
        float* hp = (float*)outv;
        float rsum[4][2], rs2[4][2];
#pragma unroll
        for (int i2 = 0; i2 < 4; i2++)
#pragma unroll
            for (int half = 0; half < 2; half++) {
                int r = m0 + wm + 16 * i2 + g + 8 * half;
                size_t ob = (size_t)win_to_orig(r) * CC;
                float ps = 0.f, pq = 0.f;
#pragma unroll
                for (int j2 = 0; j2 < 6; j2++) {
                    int c = wn + 8 * j2 + 2 * t;
                    float v0 = acc[i2][j2][half * 2 + 0] + bias[c];
                    float v1 = acc[i2][j2][half * 2 + 1] + bias[c + 1];
                    float2 a2 = *(const float2*)(aux + ob + c);
                    v0 += a2.x; v1 += a2.y;
                    *(float2*)(hp + ob + c) = make_float2(v0, v1);
                    ps += v0 + v1;
                    pq += v0 * v0 + v1 * v1;
                }
                rsum[i2][half] = ps; rs2[i2][half] = pq;
            }
#pragma unroll
        for (int i2 = 0; i2 < 4; i2++)
#pragma unroll
            for (int half = 0; half < 2; half++) {
                float s = rsum[i2][half], q = rs2[i2][half];
                s += __shfl_xor_sync(0xffffffffu, s, 1);
                s += __shfl_xor_sync(0xffffffffu, s, 2);
                q += __shfl_xor_sync(0xffffffffu, q, 1);
                q += __shfl_xor_sync(0xffffffffu, q, 2);
                rsum[i2][half] = s; rs2[i2][half] = q;
            }
        float2* red = (float2*)smc;   // smem reuse after mainloop
        __syncthreads();
        if (t == 0) {
#pragma unroll
            for (int i2 = 0; i2 < 4; i2++)
#pragma unroll
                for (int half = 0; half < 2; half++) {
                    int rl = wm + 16 * i2 + g + 8 * half;
                    red[rl * 4 + (wid >> 1)] = make_float2(rsum[i2][half], rs2[i2][half]);
                }
        }
        __syncthreads();
#pragma unroll
        for (int i2 = 0; i2 < 4; i2++)
#pragma unroll
            for (int half = 0; half < 2; half++) {
                int rl = wm + 16 * i2 + g + 8 * half;
                float s = 0.f, q = 0.f;
#pragma unroll
                for (int k = 0; k < 4; k++) {
                    float2 p = red[rl * 4 + k];
                    s += p.x; q += p.y;
                }
                float mean = s * (1.f / CC);
                float var  = q * (1.f / CC) - mean * mean;
                float rstd = rsqrtf(var + 1e-5f);
                size_t ob = (size_t)win_to_orig(m0 + rl) * CC;
#pragma unroll
                for (int j2 = 0; j2 < 6; j2++) {
                    int c = wn + 8 * j2 + 2 * t;
                    float2 hv = *(const float2*)(hp + ob + c);
                    float x0 = (hv.x - mean) * rstd * g2[c] + b2[c];
                    float x1 = (hv.y - mean) * rstd * g2[c + 1] + b2[c + 1];
                    *(uint32_t*)(xwout + ob + c) = packbf2(x0, x1);
                }
            }
    }
}

// ================= Tensor-core windowed attention =================
#define AT_THREADS 384
#define AT_SLOT    2560
#define AT_RPB_OFF (18*AT_SLOT*2)
#define AT_SMEM    (AT_RPB_OFF + 1350*4)

__global__ __launch_bounds__(AT_THREADS)
void attn_mma(const __nv_bfloat16* __restrict__ qkv, const float* __restrict__ rpb,
              __nv_bfloat16* __restrict__ outp) {
    extern __shared__ char sm[];
    uint32_t sb = smem_u32(sm);
    int w = blockIdx.x;
    int widx = w & 255;
    int wh = widx >> 4, ww = widx & 15;
    int tid = threadIdx.x, lane = tid & 31, wid = tid >> 5;

    const __nv_bfloat16* src = qkv + (size_t)w * NN * C3;
    for (int idx = tid; idx < 4608; idx += AT_THREADS) {
        int slot = idx >> 8;
        int rem = idx & 255;
        int row = rem >> 2, c = rem & 3;
        int tt = slot / 6, hh = slot - tt * 6;
        CPCA16(sb + (uint32_t)(slot * AT_SLOT + row * 40) * 2 + c * 16,
               src + (size_t)row * C3 + tt * CC + hh * HD + c * 8);
    }
    for (int idx = tid; idx < 1350; idx += AT_THREADS)
        CP4(sb + AT_RPB_OFF + idx * 4, rpb + idx);
    CPCOMMIT();
    CPWAIT(0);
    __syncthreads();

    int h = wid >> 1, half = wid & 1;
    uint32_t Qb = sb + (uint32_t)(0 * 6 + h) * AT_SLOT * 2;
    uint32_t Kb = sb + (uint32_t)(1 * 6 + h) * AT_SLOT * 2;
    uint32_t Vb = sb + (uint32_t)(2 * 6 + h) * AT_SLOT * 2;
    const float* rpbs = (const float*)(sm + AT_RPB_OFF);
    int l8 = lane & 7, msel = lane >> 3;
    int g = lane >> 2, t4 = lane & 3;

    uint32_t qf[2][2][4];
#pragma unroll
    for (int mi = 0; mi < 2; mi++)
#pragma unroll
        for (int kt = 0; kt < 2; kt++)
            ldm4(qf[mi][kt], Qb + (uint32_t)(half * 32 + 16 * mi + l8 + ((msel & 1) << 3)) * 80
                                + (uint32_t)(kt * 32 + (msel >> 1) * 16));

    float s[2][8][4];
#pragma unroll
    for (int mi = 0; mi < 2; mi++)
#pragma unroll
        for (int n2 = 0; n2 < 8; n2++)
#pragma unroll
            for (int e = 0; e < 4; e++) s[mi][n2][e] = 0.f;

#pragma unroll
    for (int nj = 0; nj < 4; nj++)
#pragma unroll
        for (int kt = 0; kt < 2; kt++) {
            uint32_t kf[4];
            ldm4(kf, Kb + (uint32_t)(nj * 16 + l8 + ((msel >> 1) << 3)) * 80
                        + (uint32_t)(kt * 32 + (msel & 1) * 16));
#pragma unroll
            for (int mi = 0; mi < 2; mi++) {
                mma_bf16(s[mi][2 * nj + 0], qf[mi][kt], kf[0], kf[1]);
                mma_bf16(s[mi][2 * nj + 1], qf[mi][kt], kf[2], kf[3]);
            }
        }

    // ---- strength-reduced bias+mask: rj==n2, cj==2*t4+par exactly ----
    int crn[8], cwp[2];
#pragma unroll
    for (int n2 = 0; n2 < 8; n2++) {
        int gj_r = wh * 8 + n2;
        crn[n2] = (gj_r < HH - WS) ? 0 : ((gj_r < HH - SHIFTV) ? 1 : 2);
    }
#pragma unroll
    for (int par = 0; par < 2; par++) {
        int gj_c = ww * 8 + 2 * t4 + par;
        cwp[par] = (gj_c < WWID - WS) ? 0 : ((gj_c < WWID - SHIFTV) ? 1 : 2);
    }

#pragma unroll
    for (int mi = 0; mi < 2; mi++) {
        int r0 = half * 32 + 16 * mi + g;
#pragma unroll
        for (int eh = 0; eh < 2; eh++) {
            int rowv = r0 + eh * 8;
            int ri = rowv >> 3, ci = rowv & 7;
            int gi_r = wh * 8 + ri, gi_c = ww * 8 + ci;
            int clsI = ((gi_r < HH - WS) ? 0 : ((gi_r < HH - SHIFTV) ? 1 : 2)) * 3
                     + ((gi_c < WWID - WS) ? 0 : ((gi_c < WWID - SHIFTV) ? 1 : 2));
#pragma unroll
            for (int par = 0; par < 2; par++) {
                int e = eh * 2 + par;
                int cj = 2 * t4 + par;
                const float* bp = rpbs + (((ri + 7) * 15 + (ci - cj + 7)) * HEADS + h);
#pragma unroll
                for (int n2 = 0; n2 < 8; n2++) {
                    float b = bp[-90 * n2];
                    float m = ((crn[n2] * 3 + cwp[par]) != clsI) ? -100.f : 0.f;
                    s[mi][n2][e] = s[mi][n2][e] * SCALE + b + m;
                }
            }
        }
        // ---- softmax (unchanged) ----
        float mx0 = -1e30f, mx1 = -1e30f;
#pragma unroll
        for (int n2 = 0; n2 < 8; n2++) {
            mx0 = fmaxf(mx0, fmaxf(s[mi][n2][0], s[mi][n2][1]));
            mx1 = fmaxf(mx1, fmaxf(s[mi][n2][2], s[mi][n2][3]));
        }
        mx0 = fmaxf(mx0, __shfl_xor_sync(0xffffffffu, mx0, 1));
        mx0 = fmaxf(mx0, __shfl_xor_sync(0xffffffffu, mx0, 2));
        mx1 = fmaxf(mx1, __shfl_xor_sync(0xffffffffu, mx1, 1));
        mx1 = fmaxf(mx1, __shfl_xor_sync(0xffffffffu, mx1, 2));
        float sum0 = 0.f, sum1 = 0.f;
#pragma unroll
        for (int n2 = 0; n2 < 8; n2++) {
            s[mi][n2][0] = __expf(s[mi][n2][0] - mx0);
            s[mi][n2][1] = __expf(s[mi][n2][1] - mx0);
            s[mi][n2][2] = __expf(s[mi][n2][2] - mx1);
            s[mi][n2][3] = __expf(s[mi][n2][3] - mx1);
            sum0 += s[mi][n2][0] + s[mi][n2][1];
            sum1 += s[mi][n2][2] + s[mi][n2][3];
        }
        sum0 += __shfl_xor_sync(0xffffffffu, sum0, 1);
        sum0 += __shfl_xor_sync(0xffffffffu, sum0, 2);
        sum1 += __shfl_xor_sync(0xffffffffu, sum1, 1);
        sum1 += __shfl_xor_sync(0xffffffffu, sum1, 2);
        float inv0 = 1.f / sum0, inv1 = 1.f / sum1;
#pragma unroll
        for (int n2 = 0; n2 < 8; n2++) {
            s[mi][n2][0] *= inv0; s[mi][n2][1] *= inv0;
            s[mi][n2][2] *= inv1; s[mi][n2][3] *= inv1;
        }
    }

    float o[2][4][4];
#pragma unroll
    for (int mi = 0; mi < 2; mi++)
#pragma unroll
        for (int d2 = 0; d2 < 4; d2++)
#pragma unroll
            for (int e = 0; e < 4; e++) o[mi][d2][e] = 0.f;

#pragma unroll
    for (int kp = 0; kp < 4; kp++) {
        uint32_t pf[2][4];
#pragma unroll
        for (int mi = 0; mi < 2; mi++) {
            pf[mi][0] = packbf2(s[mi][2 * kp + 0][0], s[mi][2 * kp + 0][1]);
            pf[mi][1] = packbf2(s[mi][2 * kp + 0][2], s[mi][2 * kp + 0][3]);
            pf[mi][2] = packbf2(s[mi][2 * kp + 1][0], s[mi][2 * kp + 1][1]);
            pf[mi][3] = packbf2(s[mi][2 * kp + 1][2], s[mi][2 * kp + 1][3]);
        }
#pragma unroll
        for (int dh = 0; dh < 2; dh++) {
            uint32_t vf[4];
            int vrow = 16 * kp + (lane & 7) + 8 * ((lane >> 3) & 1);
            ldm4t(vf, Vb + (uint32_t)vrow * 80 + (uint32_t)(dh * 32 + ((lane >> 4) << 4)));
#pragma unroll
            for (int mi = 0; mi < 2; mi++) {
                mma_bf16(o[mi][2 * dh + 0], pf[mi], vf[0], vf[1]);
                mma_bf16(o[mi][2 * dh + 1], pf[mi], vf[2], vf[3]);
            }
        }
    }

#pragma unroll
    for (int mi = 0; mi < 2; mi++) {
        int r0 = half * 32 + 16 * mi + g;
        size_t ob0 = ((size_t)w * NN + r0) * CC + h * HD;
        size_t ob1 = ((size_t)w * NN + r0 + 8) * CC + h * HD;
#pragma unroll
        for (int d2 = 0; d2 < 4; d2++) {
            int c = 8 * d2 + 2 * t4;
            *(uint32_t*)(outp + ob0 + c) = packbf2(o[mi][d2][0], o[mi][d2][1]);
            *(uint32_t*)(outp + ob1 + c) = packbf2(o[mi][d2][2], o[mi][d2][3]);
        }
    }
}

// ================= host =================
extern "C" void kernel_launch(void* const* d_in, const int* in_sizes, int n_in,
                              void* d_out, int out_size) {
    const float* x     = (const float*)d_in[0];
    const float* n1g   = (const float*)d_in[1];
    const float* n1b   = (const float*)d_in[2];
    const float* qkvw  = (const float*)d_in[3];
    const float* qkvb  = (const float*)d_in[4];
    const float* projw = (const float*)d_in[5];
    const float* projb = (const float*)d_in[6];
    const float* rpb   = (const float*)d_in[7];
    const float* n2g   = (const float*)d_in[8];
    const float* n2b   = (const float*)d_in[9];
    const float* fc1w  = (const float*)d_in[10];
    const float* fc1b  = (const float*)d_in[11];
    const float* fc2w  = (const float*)d_in[12];
    const float* fc2b  = (const float*)d_in[13];
    float* out = (float*)d_out;

    __nv_bfloat16 *xw, *qkv, *attn, *m1, *wb;
    float *h;
    cudaGetSymbolAddress((void**)&xw,   g_xw);
    cudaGetSymbolAddress((void**)&qkv,  g_qkv);
    cudaGetSymbolAddress((void**)&attn, g_attn);
    cudaGetSymbolAddress((void**)&h,    g_h);
    cudaGetSymbolAddress((void**)&m1,   g_m1);
    cudaGetSymbolAddress((void**)&wb,   g_wb);

    cudaFuncSetAttribute((const void*)bgemm<0>, cudaFuncAttributeMaxDynamicSharedMemorySize, GSMEM);
    cudaFuncSetAttribute((const void*)bgemm<1>, cudaFuncAttributeMaxDynamicSharedMemorySize, GSMEM);
    cudaFuncSetAttribute((const void*)bgemm<2>, cudaFuncAttributeMaxDynamicSharedMemorySize, GSMEM);
    cudaFuncSetAttribute((const void*)bgemm<3>, cudaFuncAttributeMaxDynamicSharedMemorySize, GSMEM);
    cudaFuncSetAttribute((const void*)attn_mma, cudaFuncAttributeMaxDynamicSharedMemorySize, AT_SMEM);

    // 0. weight conversion (single launch)
    wconv4<<<(WTOT / 4 + 255) / 256, 256>>>(qkvw, projw, fc1w, fc2w, wb);

    // 1. LN1 + shift + window partition
    ln_kernel<<<TT / 8, 256>>>(x, n1g, n1b, xw);
    // 2. QKV
    bgemm<0><<<dim3(C3 / BN, TT / BM), 256, GSMEM>>>(xw, wb + WB_QKV, qkvb, qkv, nullptr, C3, CC,
                                                     nullptr, nullptr, nullptr);
    // 3. Attention
    attn_mma<<<BWIN, AT_THREADS, AT_SMEM>>>(qkv, rpb, attn);
    // 4. Proj + residual(x) -> h; fused LN2 -> xw
    bgemm<1><<<dim3(1, TT / BM), 256, GSMEM>>>(attn, wb + WB_PROJ, projb, h, x, CC, CC,
                                               n2g, n2b, xw);
    // 5. FC1 + GELU
    bgemm<2><<<dim3(C4 / BN, TT / BM), 256, GSMEM>>>(xw, wb + WB_FC1, fc1b, m1, nullptr, C4, CC,
                                                     nullptr, nullptr, nullptr);
    // 6. FC2 + residual(h) -> out
    bgemm<3><<<dim3(1, TT / BM), 256, GSMEM>>>(m1, wb + WB_FC2, fc2b, out, h, CC, C4,
                                               nullptr, nullptr, nullptr);
}

// round 15
// speedup vs baseline: 1.0117x; 1.0117x over previous
#include <cuda_runtime.h>
#include <cuda_bf16.h>
#include <cstdint>
#include <math.h>

// ---- problem constants ----
#define BB    16
#define HH    128
#define WWID  128
#define CC    192
#define WS    8
#define SHIFTV 4
#define HEADS 6
#define NN    64
#define HD    32
#define TT    (BB*HH*WWID)   // 262144
#define NWIN  256
#define BWIN  (BB*NWIN)      // 4096
#define C3    (3*CC)         // 576
#define C4    (4*CC)         // 768
#define SCALE 0.17677669529663687f

// ---- scratch ----
__device__ __align__(16) __nv_bfloat16 g_xw  [(size_t)TT*CC];
__device__ __align__(16) __nv_bfloat16 g_qkv [(size_t)TT*C3];
__device__ __align__(16) __nv_bfloat16 g_attn[(size_t)TT*CC];
__device__ __align__(16) float         g_h   [(size_t)TT*CC];
__device__ __align__(16) __nv_bfloat16 g_m1  [(size_t)TT*C4];
__device__ __align__(16) __nv_bfloat16 g_wb  [C3*CC + CC*CC + C4*CC + CC*C4];

#define WB_QKV  0
#define WB_PROJ (C3*CC)
#define WB_FC1  (WB_PROJ + CC*CC)
#define WB_FC2  (WB_FC1 + C4*CC)

// ---- helpers ----
__device__ __forceinline__ uint32_t smem_u32(const void* p) {
    uint32_t a;
    asm("{ .reg .u64 t; cvta.to.shared.u64 t, %1; cvt.u32.u64 %0, t; }" : "=r"(a) : "l"(p));
    return a;
}
__device__ __forceinline__ uint32_t packbf2(float lo, float hi) {
    uint32_t r;
    asm("cvt.rn.bf16x2.f32 %0, %1, %2;" : "=r"(r) : "f"(hi), "f"(lo));
    return r;
}
__device__ __forceinline__ void ldm4(uint32_t r[4], uint32_t addr) {
    asm volatile("ldmatrix.sync.aligned.m8n8.x4.shared.b16 {%0,%1,%2,%3}, [%4];"
        : "=r"(r[0]), "=r"(r[1]), "=r"(r[2]), "=r"(r[3]) : "r"(addr));
}
__device__ __forceinline__ void ldm4t(uint32_t r[4], uint32_t addr) {
    asm volatile("ldmatrix.sync.aligned.m8n8.x4.trans.shared.b16 {%0,%1,%2,%3}, [%4];"
        : "=r"(r[0]), "=r"(r[1]), "=r"(r[2]), "=r"(r[3]) : "r"(addr));
}
__device__ __forceinline__ void mma_bf16(float c[4], const uint32_t a[4], uint32_t b0, uint32_t b1) {
    asm volatile("mma.sync.aligned.m16n8k16.row.col.f32.bf16.bf16.f32 "
        "{%0,%1,%2,%3},{%4,%5,%6,%7},{%8,%9},{%0,%1,%2,%3};"
        : "+f"(c[0]), "+f"(c[1]), "+f"(c[2]), "+f"(c[3])
        : "r"(a[0]), "r"(a[1]), "r"(a[2]), "r"(a[3]), "r"(b0), "r"(b1));
}
#define CP16(dst, src) asm volatile("cp.async.cg.shared.global [%0], [%1], 16;" :: "r"(dst), "l"(src))
#define CPCA16(dst, src) asm volatile("cp.async.ca.shared.global [%0], [%1], 16;" :: "r"(dst), "l"(src))
#define CP4(dst, src)  asm volatile("cp.async.ca.shared.global [%0], [%1], 4;"  :: "r"(dst), "l"(src))
#define CPCOMMIT() asm volatile("cp.async.commit_group;" ::: "memory")
#define CPWAIT(n)  asm volatile("cp.async.wait_group %0;" :: "n"(n) : "memory")

__device__ __forceinline__ int win_to_orig(int tw) {
    int n  = tw & 63;
    int bw = tw >> 6;
    int ww = bw & 15;
    int wh = (bw >> 4) & 15;
    int b  = bw >> 8;
    int ri = n >> 3, ci = n & 7;
    int r = (wh * 8 + ri + SHIFTV) & 127;
    int c = (ww * 8 + ci + SHIFTV) & 127;
    return (b << 14) + (r << 7) + c;
}

// ================= fused weight convert =================
#define WTOT (C3*CC + CC*CC + C4*CC + CC*C4)
__global__ void wconv4(const float* __restrict__ s0, const float* __restrict__ s1,
                       const float* __restrict__ s2, const float* __restrict__ s3,
                       __nv_bfloat16* __restrict__ dst) {
    int i = (blockIdx.x * 256 + threadIdx.x) * 4;
    if (i >= WTOT) return;
    const int n0 = C3 * CC, n1 = n0 + CC * CC, n2 = n1 + C4 * CC;
    const float* src;
    int off;
    if (i < n0)      { src = s0; off = i; }
    else if (i < n1) { src = s1; off = i - n0; }
    else if (i < n2) { src = s2; off = i - n1; }
    else             { src = s3; off = i - n2; }
    float4 f = *(const float4*)(src + off);
    *(uint2*)(dst + i) = make_uint2(packbf2(f.x, f.y), packbf2(f.z, f.w));
}

// ================= LN1 (gather + fp32 -> bf16) =================
__global__ void ln_kernel(const float* __restrict__ in, const float* __restrict__ gg,
                          const float* __restrict__ bb, __nv_bfloat16* __restrict__ out) {
    int warp = blockIdx.x * (blockDim.x >> 5) + (threadIdx.x >> 5);
    int lane = threadIdx.x & 31;
    int src = win_to_orig(warp);
    const float* ip = in + (size_t)src * CC;
    float v[6];
    float s = 0.f, s2 = 0.f;
#pragma unroll
    for (int k = 0; k < 6; k++) {
        v[k] = ip[lane + 32 * k];
        s += v[k]; s2 += v[k] * v[k];
    }
#pragma unroll
    for (int o = 16; o; o >>= 1) {
        s  += __shfl_xor_sync(0xffffffffu, s,  o);
        s2 += __shfl_xor_sync(0xffffffffu, s2, o);
    }
    float mean = s * (1.f / CC);
    float var  = s2 * (1.f / CC) - mean * mean;
    float rstd = rsqrtf(var + 1e-5f);
    __nv_bfloat16* op = out + (size_t)warp * CC;
#pragma unroll
    for (int k = 0; k < 6; k++) {
        int c = lane + 32 * k;
        op[c] = __float2bfloat16((v[k] - mean) * rstd * gg[c] + bb[c]);
    }
}

// ================= bf16 mma GEMM =================
#define BM 128
#define BN 192
#define BKH 64
#define AST (BM*128)
#define BST (BN*128)
#define STAGE (AST+BST)
#define GSMEM (2*STAGE)   // 81920

template<int EPI>
__global__ __launch_bounds__(256, 2)
void bgemm(const __nv_bfloat16* __restrict__ A, const __nv_bfloat16* __restrict__ W,
           const float* __restrict__ bias, void* __restrict__ outv,
           const float* __restrict__ aux, int Ntot, int K,
           const float* __restrict__ g2, const float* __restrict__ b2,
           __nv_bfloat16* __restrict__ xwout) {
    extern __shared__ char smc[];
    uint32_t sbase = smem_u32(smc);
    int tid = threadIdx.x, lane = tid & 31, wid = tid >> 5;
    int m0 = blockIdx.y * BM, n0 = blockIdx.x * BN;
    int wm = (wid & 1) * 64, wn = (wid >> 1) * 48;
    int g = lane >> 2, t = lane & 3;
    int l8 = lane & 7, msel = lane >> 3;

    float acc[4][6][4];
#pragma unroll
    for (int i = 0; i < 4; i++)
#pragma unroll
        for (int j = 0; j < 6; j++)
#pragma unroll
            for (int q = 0; q < 4; q++) acc[i][j][q] = 0.f;

    const __nv_bfloat16* Abp = A + (size_t)m0 * K;
    const __nv_bfloat16* Wbp = W + (size_t)n0 * K;

#define ISSUE(kt, buf) { \
    uint32_t sA_ = sbase + (buf) * STAGE; \
    uint32_t sB_ = sA_ + AST; \
    _Pragma("unroll") for (int i2 = 0; i2 < 4; i2++) { int id = tid + 256 * i2; \
        int row = id >> 3, cc_ = id & 7; \
        CP16(sA_ + (uint32_t)(row * 128 + ((cc_ ^ (row & 7)) * 16)), \
             Abp + (size_t)row * K + (kt) * BKH + cc_ * 8); } \
    _Pragma("unroll") for (int i2 = 0; i2 < 6; i2++) { int id = tid + 256 * i2; \
        int row = id >> 3, cc_ = id & 7; \
        CPCA16(sB_ + (uint32_t)(row * 128 + ((cc_ ^ (row & 7)) * 16)), \
             Wbp + (size_t)row * K + (kt) * BKH + cc_ * 8); } \
    CPCOMMIT(); }

#define CMP(buf) { \
    uint32_t sA_ = sbase + (buf) * STAGE; \
    uint32_t sB_ = sA_ + AST; \
    _Pragma("unroll") for (int s = 0; s < 4; s++) { \
        uint32_t af[4][4]; \
        _Pragma("unroll") for (int i2 = 0; i2 < 4; i2++) \
            ldm4(af[i2], sA_ + (uint32_t)(wm + 16 * i2 + l8 + ((msel & 1) << 3)) * 128 \
                             + (uint32_t)(((2 * s + (msel >> 1)) ^ l8) * 16)); \
        _Pragma("unroll") for (int j = 0; j < 3; j++) { \
            uint32_t bq[4]; \
            ldm4(bq, sB_ + (uint32_t)(wn + 16 * j + l8 + ((msel >> 1) << 3)) * 128 \
                         + (uint32_t)(((2 * s + (msel & 1)) ^ l8) * 16)); \
            _Pragma("unroll") for (int i2 = 0; i2 < 4; i2++) { \
                mma_bf16(acc[i2][2 * j + 0], af[i2], bq[0], bq[1]); \
                mma_bf16(acc[i2][2 * j + 1], af[i2], bq[2], bq[3]); } } } }

    const int KT = K / BKH;
    ISSUE(0, 0);
    for (int kt = 0; kt < KT; kt++) {
        if (kt + 1 < KT) { ISSUE(kt + 1, (kt + 1) & 1); CPWAIT(1); }
        else             { CPWAIT(0); }
        __syncthreads();
        CMP(kt & 1);
        __syncthreads();
    }
#undef ISSUE
#undef CMP

    if (EPI == 0 || EPI == 2) {
        __nv_bfloat16* outp = (__nv_bfloat16*)outv;
#pragma unroll
        for (int i2 = 0; i2 < 4; i2++)
#pragma unroll
            for (int half = 0; half < 2; half++) {
                int r = m0 + wm + 16 * i2 + g + 8 * half;
                size_t ob = (size_t)r * Ntot;
#pragma unroll
                for (int j2 = 0; j2 < 6; j2++) {
                    int c = n0 + wn + 8 * j2 + 2 * t;
                    float v0 = acc[i2][j2][half * 2 + 0] + bias[c];
                    float v1 = acc[i2][j2][half * 2 + 1] + bias[c + 1];
                    if (EPI == 2) {
                        v0 = 0.5f * v0 * (1.f + erff(v0 * 0.70710678118654752f));
                        v1 = 0.5f * v1 * (1.f + erff(v1 * 0.70710678118654752f));
                    }
                    *(uint32_t*)(outp + ob + c) = packbf2(v0, v1);
                }
            }
    } else if (EPI == 3) {
        float* outp = (float*)outv;
#pragma unroll
        for (int i2 = 0; i2 < 4; i2++)
#pragma unroll
            for (int half = 0; half < 2; half++) {
                int r = m0 + wm + 16 * i2 + g + 8 * half;
                size_t ob = (size_t)r * CC;
#pragma unroll
                for (int j2 = 0; j2 < 6; j2++) {
                    int c = n0 + wn + 8 * j2 + 2 * t;
                    float2 a2 = *(const float2*)(aux + ob + c);
                    float v0 = acc[i2][j2][half * 2 + 0] + bias[c] + a2.x;
                    float v1 = acc[i2][j2][half * 2 + 1] + bias[c + 1] + a2.y;
                    *(float2*)(outp + ob + c) = make_float2(v0, v1);
                }
            }
    } else {
        float* hp = (float*)outv;
        float rsum[4][2], rs2[4][2];
#pragma unroll
        for (int i2 = 0; i2 < 4; i2++)
#pragma unroll
            for (int half = 0; half < 2; half++) {
                int r = m0 + wm + 16 * i2 + g + 8 * half;
                size_t ob = (size_t)win_to_orig(r) * CC;
                float ps = 0.f, pq = 0.f;
#pragma unroll
                for (int j2 = 0; j2 < 6; j2++) {
                    int c = wn + 8 * j2 + 2 * t;
                    float v0 = acc[i2][j2][half * 2 + 0] + bias[c];
                    float v1 = acc[i2][j2][half * 2 + 1] + bias[c + 1];
                    float2 a2 = *(const float2*)(aux + ob + c);
                    v0 += a2.x; v1 += a2.y;
                    *(float2*)(hp + ob + c) = make_float2(v0, v1);
                    ps += v0 + v1;
                    pq += v0 * v0 + v1 * v1;
                }
                rsum[i2][half] = ps; rs2[i2][half] = pq;
            }
#pragma unroll
        for (int i2 = 0; i2 < 4; i2++)
#pragma unroll
            for (int half = 0; half < 2; half++) {
                float s = rsum[i2][half], q = rs2[i2][half];
                s += __shfl_xor_sync(0xffffffffu, s, 1);
                s += __shfl_xor_sync(0xffffffffu, s, 2);
                q += __shfl_xor_sync(0xffffffffu, q, 1);
                q += __shfl_xor_sync(0xffffffffu, q, 2);
                rsum[i2][half] = s; rs2[i2][half] = q;
            }
        float2* red = (float2*)smc;
        __syncthreads();
        if (t == 0) {
#pragma unroll
            for (int i2 = 0; i2 < 4; i2++)
#pragma unroll
                for (int half = 0; half < 2; half++) {
                    int rl = wm + 16 * i2 + g + 8 * half;
                    red[rl * 4 + (wid >> 1)] = make_float2(rsum[i2][half], rs2[i2][half]);
                }
        }
        __syncthreads();
#pragma unroll
        for (int i2 = 0; i2 < 4; i2++)
#pragma unroll
            for (int half = 0; half < 2; half++) {
                int rl = wm + 16 * i2 + g + 8 * half;
                float s = 0.f, q = 0.f;
#pragma unroll
                for (int k = 0; k < 4; k++) {
                    float2 p = red[rl * 4 + k];
                    s += p.x; q += p.y;
                }
                float mean = s * (1.f / CC);
                float var  = q * (1.f / CC) - mean * mean;
                float rstd = rsqrtf(var + 1e-5f);
                size_t ob = (size_t)win_to_orig(m0 + rl) * CC;
#pragma unroll
                for (int j2 = 0; j2 < 6; j2++) {
                    int c = wn + 8 * j2 + 2 * t;
                    float2 hv = *(const float2*)(hp + ob + c);
                    float x0 = (hv.x - mean) * rstd * g2[c] + b2[c];
                    float x1 = (hv.y - mean) * rstd * g2[c + 1] + b2[c + 1];
                    *(uint32_t*)(xwout + ob + c) = packbf2(x0, x1);
                }
            }
    }
}

// ================= Tensor-core windowed attention (24 warps: head x quarter) =================
#define AT_THREADS 768
#define AT_SLOT    2560
#define AT_RPB_OFF (18*AT_SLOT*2)
#define AT_SMEM    (AT_RPB_OFF + 1350*4)

__global__ __launch_bounds__(AT_THREADS)
void attn_mma(const __nv_bfloat16* __restrict__ qkv, const float* __restrict__ rpb,
              __nv_bfloat16* __restrict__ outp) {
    extern __shared__ char sm[];
    uint32_t sb = smem_u32(sm);
    int w = blockIdx.x;
    int widx = w & 255;
    int wh = widx >> 4, ww = widx & 15;
    int tid = threadIdx.x, lane = tid & 31, wid = tid >> 5;

    const __nv_bfloat16* src = qkv + (size_t)w * NN * C3;
#pragma unroll
    for (int i = 0; i < 6; i++) {
        int idx = tid + AT_THREADS * i;
        int slot = idx >> 8;
        int rem = idx & 255;
        int row = rem >> 2, c = rem & 3;
        int tt = slot / 6, hh = slot - tt * 6;
        CPCA16(sb + (uint32_t)(slot * AT_SLOT + row * 40) * 2 + c * 16,
               src + (size_t)row * C3 + tt * CC + hh * HD + c * 8);
    }
    for (int idx = tid; idx < 1350; idx += AT_THREADS)
        CP4(sb + AT_RPB_OFF + idx * 4, rpb + idx);
    CPCOMMIT();
    CPWAIT(0);
    __syncthreads();

    int h = wid >> 2, quar = wid & 3;       // head, row-quarter (16 rows each)
    int r0q = quar * 16;
    uint32_t Qb = sb + (uint32_t)(0 * 6 + h) * AT_SLOT * 2;
    uint32_t Kb = sb + (uint32_t)(1 * 6 + h) * AT_SLOT * 2;
    uint32_t Vb = sb + (uint32_t)(2 * 6 + h) * AT_SLOT * 2;
    const float* rpbs = (const float*)(sm + AT_RPB_OFF);
    int l8 = lane & 7, msel = lane >> 3;
    int g = lane >> 2, t4 = lane & 3;

    // ---- Q fragments: 16 rows (m16k32) ----
    uint32_t qf[2][4];
#pragma unroll
    for (int kt = 0; kt < 2; kt++)
        ldm4(qf[kt], Qb + (uint32_t)(r0q + l8 + ((msel & 1) << 3)) * 80
                        + (uint32_t)(kt * 32 + (msel >> 1) * 16));

    // ---- S = Q @ K^T ----
    float s[8][4];
#pragma unroll
    for (int n2 = 0; n2 < 8; n2++)
#pragma unroll
        for (int e = 0; e < 4; e++) s[n2][e] = 0.f;

#pragma unroll
    for (int nj = 0; nj < 4; nj++)
#pragma unroll
        for (int kt = 0; kt < 2; kt++) {
            uint32_t kf[4];
            ldm4(kf, Kb + (uint32_t)(nj * 16 + l8 + ((msel >> 1) << 3)) * 80
                        + (uint32_t)(kt * 32 + (msel & 1) * 16));
            mma_bf16(s[2 * nj + 0], qf[kt], kf[0], kf[1]);
            mma_bf16(s[2 * nj + 1], qf[kt], kf[2], kf[3]);
        }

    // ---- strength-reduced bias+mask ----
    int crn[8], cwp[2];
#pragma unroll
    for (int n2 = 0; n2 < 8; n2++) {
        int gj_r = wh * 8 + n2;
        crn[n2] = (gj_r < HH - WS) ? 0 : ((gj_r < HH - SHIFTV) ? 1 : 2);
    }
#pragma unroll
    for (int par = 0; par < 2; par++) {
        int gj_c = ww * 8 + 2 * t4 + par;
        cwp[par] = (gj_c < WWID - WS) ? 0 : ((gj_c < WWID - SHIFTV) ? 1 : 2);
    }

    int r0 = r0q + g;
#pragma unroll
    for (int eh = 0; eh < 2; eh++) {
        int rowv = r0 + eh * 8;
        int ri = rowv >> 3, ci = rowv & 7;
        int gi_r = wh * 8 + ri, gi_c = ww * 8 + ci;
        int clsI = ((gi_r < HH - WS) ? 0 : ((gi_r < HH - SHIFTV) ? 1 : 2)) * 3
                 + ((gi_c < WWID - WS) ? 0 : ((gi_c < WWID - SHIFTV) ? 1 : 2));
#pragma unroll
        for (int par = 0; par < 2; par++) {
            int e = eh * 2 + par;
            int cj = 2 * t4 + par;
            const float* bp = rpbs + (((ri + 7) * 15 + (ci - cj + 7)) * HEADS + h);
#pragma unroll
            for (int n2 = 0; n2 < 8; n2++) {
                float b = bp[-90 * n2];
                float m = ((crn[n2] * 3 + cwp[par]) != clsI) ? -100.f : 0.f;
                s[n2][e] = s[n2][e] * SCALE + b + m;
            }
        }
    }

    // ---- softmax ----
    float mx0 = -1e30f, mx1 = -1e30f;
#pragma unroll
    for (int n2 = 0; n2 < 8; n2++) {
        mx0 = fmaxf(mx0, fmaxf(s[n2][0], s[n2][1]));
        mx1 = fmaxf(mx1, fmaxf(s[n2][2], s[n2][3]));
    }
    mx0 = fmaxf(mx0, __shfl_xor_sync(0xffffffffu, mx0, 1));
    mx0 = fmaxf(mx0, __shfl_xor_sync(0xffffffffu, mx0, 2));
    mx1 = fmaxf(mx1, __shfl_xor_sync(0xffffffffu, mx1, 1));
    mx1 = fmaxf(mx1, __shfl_xor_sync(0xffffffffu, mx1, 2));
    float sum0 = 0.f, sum1 = 0.f;
#pragma unroll
    for (int n2 = 0; n2 < 8; n2++) {
        s[n2][0] = __expf(s[n2][0] - mx0);
        s[n2][1] = __expf(s[n2][1] - mx0);
        s[n2][2] = __expf(s[n2][2] - mx1);
        s[n2][3] = __expf(s[n2][3] - mx1);
        sum0 += s[n2][0] + s[n2][1];
        sum1 += s[n2][2] + s[n2][3];
    }
    sum0 += __shfl_xor_sync(0xffffffffu, sum0, 1);
    sum0 += __shfl_xor_sync(0xffffffffu, sum0, 2);
    sum1 += __shfl_xor_sync(0xffffffffu, sum1, 1);
    sum1 += __shfl_xor_sync(0xffffffffu, sum1, 2);
    float inv0 = 1.f / sum0, inv1 = 1.f / sum1;
#pragma unroll
    for (int n2 = 0; n2 < 8; n2++) {
        s[n2][0] *= inv0; s[n2][1] *= inv0;
        s[n2][2] *= inv1; s[n2][3] *= inv1;
    }

    // ---- O = P @ V ----
    float o[4][4];
#pragma unroll
    for (int d2 = 0; d2 < 4; d2++)
#pragma unroll
        for (int e = 0; e < 4; e++) o[d2][e] = 0.f;

#pragma unroll
    for (int kp = 0; kp < 4; kp++) {
        uint32_t pf[4];
        pf[0] = packbf2(s[2 * kp + 0][0], s[2 * kp + 0][1]);
        pf[1] = packbf2(s[2 * kp + 0][2], s[2 * kp + 0][3]);
        pf[2] = packbf2(s[2 * kp + 1][0], s[2 * kp + 1][1]);
        pf[3] = packbf2(s[2 * kp + 1][2], s[2 * kp + 1][3]);
#pragma unroll
        for (int dh = 0; dh < 2; dh++) {
            uint32_t vf[4];
            int vrow = 16 * kp + (lane & 7) + 8 * ((lane >> 3) & 1);
            ldm4t(vf, Vb + (uint32_t)vrow * 80 + (uint32_t)(dh * 32 + ((lane >> 4) << 4)));
            mma_bf16(o[2 * dh + 0], pf, vf[0], vf[1]);
            mma_bf16(o[2 * dh + 1], pf, vf[2], vf[3]);
        }
    }

    // ---- store ----
    size_t ob0 = ((size_t)w * NN + r0) * CC + h * HD;
    size_t ob1 = ((size_t)w * NN + r0 + 8) * CC + h * HD;
#pragma unroll
    for (int d2 = 0; d2 < 4; d2++) {
        int c = 8 * d2 + 2 * t4;
        *(uint32_t*)(outp + ob0 + c) = packbf2(o[d2][0], o[d2][1]);
        *(uint32_t*)(outp + ob1 + c) = packbf2(o[d2][2], o[d2][3]);
    }
}

// ================= host =================
extern "C" void kernel_launch(void* const* d_in, const int* in_sizes, int n_in,
                              void* d_out, int out_size) {
    const float* x     = (const float*)d_in[0];
    const float* n1g   = (const float*)d_in[1];
    const float* n1b   = (const float*)d_in[2];
    const float* qkvw  = (const float*)d_in[3];
    const float* qkvb  = (const float*)d_in[4];
    const float* projw = (const float*)d_in[5];
    const float* projb = (const float*)d_in[6];
    const float* rpb   = (const float*)d_in[7];
    const float* n2g   = (const float*)d_in[8];
    const float* n2b   = (const float*)d_in[9];
    const float* fc1w  = (const float*)d_in[10];
    const float* fc1b  = (const float*)d_in[11];
    const float* fc2w  = (const float*)d_in[12];
    const float* fc2b  = (const float*)d_in[13];
    float* out = (float*)d_out;

    __nv_bfloat16 *xw, *qkv, *attn, *m1, *wb;
    float *h;
    cudaGetSymbolAddress((void**)&xw,   g_xw);
    cudaGetSymbolAddress((void**)&qkv,  g_qkv);
    cudaGetSymbolAddress((void**)&attn, g_attn);
    cudaGetSymbolAddress((void**)&h,    g_h);
    cudaGetSymbolAddress((void**)&m1,   g_m1);
    cudaGetSymbolAddress((void**)&wb,   g_wb);

    cudaFuncSetAttribute((const void*)bgemm<0>, cudaFuncAttributeMaxDynamicSharedMemorySize, GSMEM);
    cudaFuncSetAttribute((const void*)bgemm<1>, cudaFuncAttributeMaxDynamicSharedMemorySize, GSMEM);
    cudaFuncSetAttribute((const void*)bgemm<2>, cudaFuncAttributeMaxDynamicSharedMemorySize, GSMEM);
    cudaFuncSetAttribute((const void*)bgemm<3>, cudaFuncAttributeMaxDynamicSharedMemorySize, GSMEM);
    cudaFuncSetAttribute((const void*)attn_mma, cudaFuncAttributeMaxDynamicSharedMemorySize, AT_SMEM);

    // 0. weight conversion (single launch)
    wconv4<<<(WTOT / 4 + 255) / 256, 256>>>(qkvw, projw, fc1w, fc2w, wb);

    // 1. LN1 + shift + window partition
    ln_kernel<<<TT / 8, 256>>>(x, n1g, n1b, xw);
    // 2. QKV
    bgemm<0><<<dim3(C3 / BN, TT / BM), 256, GSMEM>>>(xw, wb + WB_QKV, qkvb, qkv, nullptr, C3, CC,
                                                     nullptr, nullptr, nullptr);
    // 3. Attention (24 warps/block)
    attn_mma<<<BWIN, AT_THREADS, AT_SMEM>>>(qkv, rpb, attn);
    // 4. Proj + residual(x) -> h; fused LN2 -> xw
    bgemm<1><<<dim3(1, TT / BM), 256, GSMEM>>>(attn, wb + WB_PROJ, projb, h, x, CC, CC,
                                               n2g, n2b, xw);
    // 5. FC1 + GELU
    bgemm<2><<<dim3(C4 / BN, TT / BM), 256, GSMEM>>>(xw, wb + WB_FC1, fc1b, m1, nullptr, C4, CC,
                                                     nullptr, nullptr, nullptr);
    // 6. FC2 + residual(h) -> out
    bgemm<3><<<dim3(1, TT / BM), 256, GSMEM>>>(m1, wb + WB_FC2, fc2b, out, h, CC, C4,
                                               nullptr, nullptr, nullptr);
}